// round 14
// baseline (speedup 1.0000x reference)
#include <cuda_runtime.h>
#include <cstdint>
#include <cstddef>

// x_{t+1} = x_t + 0.1*tanh([x_t,u_t]@W1 + b1)@W2 + b2
// B=1024, T=200, SD=64, CD=32, H=512.
// 128 persistent CTAs x 256 threads. Thread owns col-pair (2tid, 2tid+1).
// K-PAIR PACKING: W1 pre-packed {W1[2kp][c],W1[2kp+1][c]} (prep kernel,
// 16B-aligned ulonglong2 global); inputs staged {in[2kp][r],in[2kp+1][r]}
// -> phase-A FFMA2 operands come packed from memory, no dup movs. 16
// kpairs persistent in regs, 32 streamed (double-buffered LDG.128).
// Phase B fused strips, warp self-consistent (syncwarp). MUFU.TANH.

typedef unsigned long long u64;

static constexpr int   TSTEPS = 200;
static constexpr int   SDIM   = 64;
static constexpr int   CDIM   = 32;
static constexpr int   HDIM   = 512;
static constexpr int   ROWS   = 8;
static constexpr int   NBLK   = 1024 / ROWS;   // 128
static constexpr int   NTHR   = 256;
static constexpr float DTC    = 0.1f;
static constexpr int   OSTRIDE = (TSTEPS + 1) * SDIM;
static constexpr int   NKP    = 48;            // k-pairs (96 k)

static constexpr int W2P_U = HDIM * 32;       // 16384: W2 rows as u64 i-pairs
static constexpr int HA_U  = HDIM * 2;        //  1024: {rows01,rows23}/col
static constexpr int HB_U  = HDIM * 2;        //  1024: {rows45,rows67}/col
static constexpr int IN_U  = NKP * 10;        //   480: in2[kp][r], stride 10
static constexpr int PS_U  = 8 * 258;         //  2064: psd[w][rp*64+i]
static constexpr int B2_U  = 32;              //  64 floats = 32 u64 (FIXED)
static constexpr size_t SMEM_BYTES =
    (size_t)(W2P_U + HA_U + HB_U + IN_U + PS_U + B2_U) * 8;  // 168,064 B

// 16-byte aligned by element type; indexed in PAIR units:
// g_W1p[kp*256 + cp] = cols (2cp, 2cp+1) of k-pair kp.
__device__ ulonglong2 g_W1p[NKP * HDIM / 2];

__device__ __forceinline__ u64 ffma2(u64 a, u64 b, u64 c) {
    u64 d;
    asm("fma.rn.f32x2 %0, %1, %2, %3;" : "=l"(d) : "l"(a), "l"(b), "l"(c));
    return d;
}
__device__ __forceinline__ u64 fadd2(u64 a, u64 b) {
    u64 d;
    asm("add.rn.f32x2 %0, %1, %2;" : "=l"(d) : "l"(a), "l"(b));
    return d;
}
__device__ __forceinline__ u64 pack2(float lo, float hi) {
    u64 d;
    asm("mov.b64 %0, {%1, %2};" : "=l"(d) : "r"(__float_as_int(lo)), "r"(__float_as_int(hi)));
    return d;
}
__device__ __forceinline__ u64 dupf(float f) {
    u64 d;
    asm("mov.b64 %0, {%1, %1};" : "=l"(d) : "r"(__float_as_int(f)));
    return d;
}
__device__ __forceinline__ float2 unpack2(u64 d) {
    int lo, hi;
    asm("mov.b64 {%0, %1}, %2;" : "=r"(lo), "=r"(hi) : "l"(d));
    return make_float2(__int_as_float(lo), __int_as_float(hi));
}
__device__ __forceinline__ float tanh_fast(float x) {
    float y;
    asm("tanh.approx.f32 %0, %1;" : "=f"(y) : "f"(x));
    return y;
}
// combine k-even/k-odd partials + bias, tanh
__device__ __forceinline__ float hfin(u64 acc, float b) {
    float2 f = unpack2(acc);
    return tanh_fast(f.x + f.y + b);
}

__global__ void prep_kernel(const float* __restrict__ W1) {
    int idx = blockIdx.x * blockDim.x + threadIdx.x;   // pair-unit index
    if (idx < NKP * HDIM / 2) {
        int kp = idx >> 8;            // 0..47
        int cp = idx & 255;           // col pair 0..255
        int c = 2 * cp;
        ulonglong2 v;
        v.x = pack2(W1[(2 * kp) * HDIM + c],     W1[(2 * kp + 1) * HDIM + c]);
        v.y = pack2(W1[(2 * kp) * HDIM + c + 1], W1[(2 * kp + 1) * HDIM + c + 1]);
        g_W1p[idx] = v;
    }
}

__global__ void __launch_bounds__(NTHR, 1)
rollout_kernel(const float* __restrict__ x0,
               const float* __restrict__ controls,
               const float* __restrict__ W1,
               const float* __restrict__ b1,
               const float* __restrict__ W2,
               const float* __restrict__ b2,
               float* __restrict__ out)
{
    extern __shared__ u64 sm[];
    u64*   W2p = sm;                 // [k][32] {W2[k][2i],W2[k][2i+1]}
    u64*   hA  = W2p + W2P_U;        // [2c]={r0,r1}, [2c+1]={r2,r3}
    u64*   hB  = hA + HA_U;          // [2c]={r4,r5}, [2c+1]={r6,r7}
    u64*   in2 = hB + HB_U;          // [kp*10 + r] = {in_2kp_r, in_2kp+1_r}
    u64*   psd = in2 + IN_U;         // [w][rp*64+i], stride 258
    float* b2f = (float*)(psd + PS_U);   // 64 floats

    const int tid  = threadIdx.x;
    const int lane = tid & 31;
    const int w    = tid >> 5;
    const int b0   = blockIdx.x * ROWS;
    const int c0   = 2 * tid;        // owned cols c0, c0+1
    const int rE   = w;              // epilogue row = warp id

    // ---- prologue ----
    {
        const ulonglong2* src = (const ulonglong2*)W2;
        ulonglong2* dst = (ulonglong2*)W2p;
        #pragma unroll
        for (int i = tid; i < W2P_U / 2; i += NTHR) dst[i] = src[i];
    }
    if (tid < SDIM) b2f[tid] = b2[tid];

    const float b1c0 = b1[c0];
    const float b1c1 = b1[c0 + 1];

    // persistent W1 kpairs 0..15 (packed {k-even,k-odd} for cols c0,c0+1)
    ulonglong2 wper[16];
    #pragma unroll
    for (int kp = 0; kp < 16; ++kp)
        wper[kp] = g_W1p[kp * 256 + tid];
    // streamed kpairs 16..47 (8 blocks of 4), double-buffered
    ulonglong2 wbuf[2][4];
    #pragma unroll
    for (int j = 0; j < 4; ++j)
        wbuf[0][j] = g_W1p[(16 + j) * 256 + tid];

    // stage x0 (k-pair layout), u(0); emit states[:,0,:]
    {
        int r = rE;   // thread (lane=ipair, r)
        in2[lane * 10 + r] = pack2(x0[(b0 + r) * SDIM + 2 * lane],
                                   x0[(b0 + r) * SDIM + 2 * lane + 1]);
        *(float2*)&out[(size_t)(b0 + r) * OSTRIDE + 2 * lane] =
            *(const float2*)&x0[(b0 + r) * SDIM + 2 * lane];
    }
    if (tid < 128) {
        int jp = tid & 15, r = tid >> 4;
        in2[(32 + jp) * 10 + r] =
            pack2(controls[(size_t)(b0 + r) * TSTEPS * CDIM + 2 * jp],
                  controls[(size_t)(b0 + r) * TSTEPS * CDIM + 2 * jp + 1]);
    }
    __syncthreads();

    const int kb = 64 * w;           // phase-B strip: this warp's own cols

    for (int t = 0; t < TSTEPS; ++t) {
        // prefetch next-step controls (k-pair packed)
        float un0 = 0.0f, un1 = 0.0f;
        if (tid < 128 && t + 1 < TSTEPS) {
            int jp = tid & 15, r = tid >> 4;
            const float* cp = &controls[(size_t)(b0 + r) * TSTEPS * CDIM
                                        + (size_t)(t + 1) * CDIM + 2 * jp];
            un0 = cp[0];
            un1 = cp[1];
        }

        // ---- Phase A: cols (c0, c0+1), k-pair lanes, 8 rows ----
        u64 a0[8], a1[8];
        #pragma unroll
        for (int q = 0; q < 8; ++q) { a0[q] = 0ull; a1[q] = 0ull; }
        #pragma unroll
        for (int kp = 0; kp < 16; ++kp) {
            const u64* base = &in2[kp * 10];
            ulonglong2 u01 = *(const ulonglong2*)(base);
            ulonglong2 u23 = *(const ulonglong2*)(base + 2);
            ulonglong2 u45 = *(const ulonglong2*)(base + 4);
            ulonglong2 u67 = *(const ulonglong2*)(base + 6);
            u64 w0 = wper[kp].x, w1 = wper[kp].y;
            a0[0] = ffma2(u01.x, w0, a0[0]);  a1[0] = ffma2(u01.x, w1, a1[0]);
            a0[1] = ffma2(u01.y, w0, a0[1]);  a1[1] = ffma2(u01.y, w1, a1[1]);
            a0[2] = ffma2(u23.x, w0, a0[2]);  a1[2] = ffma2(u23.x, w1, a1[2]);
            a0[3] = ffma2(u23.y, w0, a0[3]);  a1[3] = ffma2(u23.y, w1, a1[3]);
            a0[4] = ffma2(u45.x, w0, a0[4]);  a1[4] = ffma2(u45.x, w1, a1[4]);
            a0[5] = ffma2(u45.y, w0, a0[5]);  a1[5] = ffma2(u45.y, w1, a1[5]);
            a0[6] = ffma2(u67.x, w0, a0[6]);  a1[6] = ffma2(u67.x, w1, a1[6]);
            a0[7] = ffma2(u67.y, w0, a0[7]);  a1[7] = ffma2(u67.y, w1, a1[7]);
        }
        #pragma unroll
        for (int blk = 0; blk < 8; ++blk) {
            const int cur = blk & 1;
            const int kn = 16 + 4 * ((blk + 1) & 7);   // wraps for next step
            #pragma unroll
            for (int j = 0; j < 4; ++j)
                wbuf[cur ^ 1][j] = g_W1p[(kn + j) * 256 + tid];
            #pragma unroll
            for (int j = 0; j < 4; ++j) {
                const int kp = 16 + 4 * blk + j;
                const u64* base = &in2[kp * 10];
                ulonglong2 u01 = *(const ulonglong2*)(base);
                ulonglong2 u23 = *(const ulonglong2*)(base + 2);
                ulonglong2 u45 = *(const ulonglong2*)(base + 4);
                ulonglong2 u67 = *(const ulonglong2*)(base + 6);
                u64 w0 = wbuf[cur][j].x, w1 = wbuf[cur][j].y;
                a0[0] = ffma2(u01.x, w0, a0[0]);  a1[0] = ffma2(u01.x, w1, a1[0]);
                a0[1] = ffma2(u01.y, w0, a0[1]);  a1[1] = ffma2(u01.y, w1, a1[1]);
                a0[2] = ffma2(u23.x, w0, a0[2]);  a1[2] = ffma2(u23.x, w1, a1[2]);
                a0[3] = ffma2(u23.y, w0, a0[3]);  a1[3] = ffma2(u23.y, w1, a1[3]);
                a0[4] = ffma2(u45.x, w0, a0[4]);  a1[4] = ffma2(u45.x, w1, a1[4]);
                a0[5] = ffma2(u45.y, w0, a0[5]);  a1[5] = ffma2(u45.y, w1, a1[5]);
                a0[6] = ffma2(u67.x, w0, a0[6]);  a1[6] = ffma2(u67.x, w1, a1[6]);
                a0[7] = ffma2(u67.y, w0, a0[7]);  a1[7] = ffma2(u67.y, w1, a1[7]);
            }
        }
        {   // combine even+odd k partials, +b1, tanh, store row-pair layout
            float h0[8], h1[8];
            #pragma unroll
            for (int r = 0; r < 8; ++r) {
                h0[r] = hfin(a0[r], b1c0);
                h1[r] = hfin(a1[r], b1c1);
            }
            *(ulonglong2*)&hA[2 * c0] =
                make_ulonglong2(pack2(h0[0], h0[1]), pack2(h0[2], h0[3]));
            *(ulonglong2*)&hA[2 * c0 + 2] =
                make_ulonglong2(pack2(h1[0], h1[1]), pack2(h1[2], h1[3]));
            *(ulonglong2*)&hB[2 * c0] =
                make_ulonglong2(pack2(h0[4], h0[5]), pack2(h0[6], h0[7]));
            *(ulonglong2*)&hB[2 * c0 + 2] =
                make_ulonglong2(pack2(h1[4], h1[5]), pack2(h1[6], h1[7]));
        }
        __syncwarp();   // phase B reads only this warp's own cols

        // ---- Phase B: strip kb..kb+63 fused halves, lane i-pair ----
        u64 c0a[4], c1a[4];
        #pragma unroll
        for (int q = 0; q < 4; ++q) { c0a[q] = 0ull; c1a[q] = 0ull; }
        #pragma unroll 8
        for (int q = 0; q < 32; ++q) {
            const int k1 = kb + q;
            const int k2 = kb + 32 + q;
            ulonglong2 ha1 = *(const ulonglong2*)&hA[2 * k1];
            ulonglong2 hb1 = *(const ulonglong2*)&hB[2 * k1];
            ulonglong2 ha2 = *(const ulonglong2*)&hA[2 * k2];
            ulonglong2 hb2 = *(const ulonglong2*)&hB[2 * k2];
            float2 wv1 = unpack2(W2p[k1 * 32 + lane]);
            float2 wv2 = unpack2(W2p[k2 * 32 + lane]);
            u64 p0 = dupf(wv1.x), p1 = dupf(wv1.y);
            u64 q0 = dupf(wv2.x), q1 = dupf(wv2.y);
            c0a[0] = ffma2(ha1.x, p0, c0a[0]);
            c0a[1] = ffma2(ha1.y, p0, c0a[1]);
            c0a[2] = ffma2(hb1.x, p0, c0a[2]);
            c0a[3] = ffma2(hb1.y, p0, c0a[3]);
            c1a[0] = ffma2(ha1.x, p1, c1a[0]);
            c1a[1] = ffma2(ha1.y, p1, c1a[1]);
            c1a[2] = ffma2(hb1.x, p1, c1a[2]);
            c1a[3] = ffma2(hb1.y, p1, c1a[3]);
            c0a[0] = ffma2(ha2.x, q0, c0a[0]);
            c0a[1] = ffma2(ha2.y, q0, c0a[1]);
            c0a[2] = ffma2(hb2.x, q0, c0a[2]);
            c0a[3] = ffma2(hb2.y, q0, c0a[3]);
            c1a[0] = ffma2(ha2.x, q1, c1a[0]);
            c1a[1] = ffma2(ha2.y, q1, c1a[1]);
            c1a[2] = ffma2(hb2.x, q1, c1a[2]);
            c1a[3] = ffma2(hb2.y, q1, c1a[3]);
        }
        {   // psd[w][rp*64 + i]: lane stores i-pair as ulonglong2
            u64* p = &psd[w * 258 + 2 * lane];
            *(ulonglong2*)(p)       = make_ulonglong2(c0a[0], c1a[0]);
            *(ulonglong2*)(p + 64)  = make_ulonglong2(c0a[1], c1a[1]);
            *(ulonglong2*)(p + 128) = make_ulonglong2(c0a[2], c1a[2]);
            *(ulonglong2*)(p + 192) = make_ulonglong2(c0a[3], c1a[3]);
        }
        __syncthreads();

        // ---- Epilogue: thread (i-pair=lane, row=warp) ----
        {
            const int r = rE, rp = r >> 1;
            ulonglong2 s = *(const ulonglong2*)&psd[rp * 64 + 2 * lane];
            #pragma unroll
            for (int q = 1; q < 8; ++q) {
                ulonglong2 p = *(const ulonglong2*)&psd[q * 258 + rp * 64 + 2 * lane];
                s.x = fadd2(s.x, p.x);
                s.y = fadd2(s.y, p.y);
            }
            float2 fA = unpack2(s.x);   // i=2l: {r_even, r_odd}
            float2 fB = unpack2(s.y);   // i=2l+1
            float selA = (r & 1) ? fA.y : fA.x;
            float selB = (r & 1) ? fB.y : fB.x;
            float2 bb = *(const float2*)&b2f[2 * lane];
            float2 xo = unpack2(in2[lane * 10 + r]);
            float xn0 = xo.x + DTC * (selA + bb.x);
            float xn1 = xo.y + DTC * (selB + bb.y);
            in2[lane * 10 + r] = pack2(xn0, xn1);
            *(float2*)&out[(size_t)(b0 + r) * OSTRIDE
                           + (size_t)(t + 1) * SDIM + 2 * lane] =
                make_float2(xn0, xn1);
        }
        if (tid < 128 && t + 1 < TSTEPS) {
            int jp = tid & 15, r = tid >> 4;
            in2[(32 + jp) * 10 + r] = pack2(un0, un1);
        }
        __syncthreads();
    }
}

extern "C" void kernel_launch(void* const* d_in, const int* in_sizes, int n_in,
                              void* d_out, int out_size) {
    const float* x0       = (const float*)d_in[0];
    const float* controls = (const float*)d_in[1];
    const float* W1       = (const float*)d_in[2];
    const float* b1       = (const float*)d_in[3];
    const float* W2       = (const float*)d_in[4];
    const float* b2       = (const float*)d_in[5];
    float* out = (float*)d_out;

    static bool attr_set = false;
    if (!attr_set) {
        cudaFuncSetAttribute(rollout_kernel,
                             cudaFuncAttributeMaxDynamicSharedMemorySize,
                             (int)SMEM_BYTES);
        attr_set = true;
    }
    prep_kernel<<<(NKP * HDIM / 2 + 255) / 256, 256>>>(W1);
    rollout_kernel<<<NBLK, NTHR, SMEM_BYTES>>>(x0, controls, W1, b1, W2, b2, out);
}